// round 10
// baseline (speedup 1.0000x reference)
#include <cuda_runtime.h>

#define NN 50000
#define NE 800000
#define NG 64
#define DIM 128
#define OD 16
#define SCAN_CH 512
#define SCAN_NB ((NN + SCAN_CH - 1) / SCAN_CH)   // 98

// Scratch (device globals — no allocation allowed)
__device__ __align__(16) float g_h[NN * DIM];     // GEMM output / agg input
__device__ __align__(16) float g_a[NN * DIM];     // aggregation result
__device__ float g_dis[NN];                       // deg^-1/2
__device__ int   g_deg[NN];
__device__ int   g_rowptr[NN + 1];
__device__ int   g_cur[NN];
__device__ int   g_csrc[NE];                      // src per CSR slot (grouped by dst)
__device__ float g_cnorm[NE];                     // dis[s]*dis[d] per CSR slot
__device__ int   g_bsum[SCAN_NB];
__device__ int   g_boff[SCAN_NB];
__device__ __align__(16) float g_pool[NG * DIM];
__device__ int   g_cnt[NG];

// ---------------------------------------------------------------- zero scratch
__global__ void k_zero() {
    int i = blockIdx.x * blockDim.x + threadIdx.x;
    if (i < NN) g_deg[i] = 0;
    if (i < NG * DIM) g_pool[i] = 0.f;
    if (i < NG) g_cnt[i] = 0;
}

// ---------------------------------------------------------------- degree
__global__ void k_deg(const int* __restrict__ dst) {
    int e = blockIdx.x * blockDim.x + threadIdx.x;
    if (e < NE) atomicAdd(&g_deg[dst[e]], 1);
}

// ---------------------------------------------------------------- CSR build: scan
__global__ void k_scan1() {            // per-block sums of g_deg
    __shared__ int s[SCAN_CH];
    int b = blockIdx.x, t = threadIdx.x, i = b * SCAN_CH + t;
    s[t] = (i < NN) ? g_deg[i] : 0;
    __syncthreads();
#pragma unroll
    for (int off = SCAN_CH / 2; off > 0; off >>= 1) {
        if (t < off) s[t] += s[t + off];
        __syncthreads();
    }
    if (t == 0) g_bsum[b] = s[0];
}

__global__ void k_scan2() {            // exclusive scan of block sums (1 block)
    __shared__ int s[SCAN_NB];
    int t = threadIdx.x;
    if (t < SCAN_NB) s[t] = g_bsum[t];
    __syncthreads();
    if (t == 0) {
        int acc = 0;
        for (int i = 0; i < SCAN_NB; i++) { g_boff[i] = acc; acc += s[i]; }
    }
}

__global__ void k_scan3() {            // intra-block exclusive scan + offset (+dis)
    __shared__ int s[SCAN_CH];
    int b = blockIdx.x, t = threadIdx.x, i = b * SCAN_CH + t;
    int v = (i < NN) ? g_deg[i] : 0;
    s[t] = v;
    __syncthreads();
#pragma unroll
    for (int off = 1; off < SCAN_CH; off <<= 1) {
        int x = (t >= off) ? s[t - off] : 0;
        __syncthreads();
        s[t] += x;
        __syncthreads();
    }
    int excl = s[t] - v + g_boff[b];
    if (i < NN) {
        g_rowptr[i] = excl;
        g_cur[i] = excl;
        g_dis[i] = rsqrtf((float)(v + 1));   // +1 self loop, always > 0
    }
    if (i == NN - 1) g_rowptr[NN] = excl + v;
}

// ---------------------------------------------------------------- CSR fill
__global__ void k_fill(const int* __restrict__ src, const int* __restrict__ dst) {
    int e = blockIdx.x * blockDim.x + threadIdx.x;
    if (e >= NE) return;
    int s = src[e], d = dst[e];
    int p = atomicAdd(&g_cur[d], 1);
    g_csrc[p] = s;
    g_cnorm[p] = g_dis[s] * g_dis[d];
}

// ---------------------------------------------------------------- GEMM (packed FFMA2)
// g_h[M,128] = op(src)[M,128] @ W[128,128]
// sel==0: src = X (raw).  sel==1: src = relu(g_a + bias)
// Accumulate over k in pairs using fma.rn.f32x2 on b64 regs:
//   acc2 = {sum over even k, sum over odd k}; final = lo + hi.
__global__ void __launch_bounds__(256, 2)
k_gemm(const float* __restrict__ X, const float* __restrict__ W,
       const float* __restrict__ bias, int sel) {
    extern __shared__ char smemraw[];
    unsigned long long* sW2 = (unsigned long long*)smemraw;      // [64 kp][128 c] = 64 KB
    float* sX = (float*)(smemraw + 64 * 128 * 8);                // [64][128] = 32 KB
    float* sW2f = (float*)sW2;
    int tid = threadIdx.x;            // 256 threads
    int row0 = blockIdx.x * 64;

    // load W, scatter into k-paired layout: sW2[kp*128 + c] = {W[2kp][c], W[2kp+1][c]}
    const float4* W4 = (const float4*)W;
#pragma unroll
    for (int i = 0; i < 16; i++) {
        int idx = tid + 256 * i;        // float4 index; k = idx>>5, c = (idx&31)*4
        int k = idx >> 5, c = (idx & 31) * 4;
        float4 v = W4[idx];
        int base = ((k >> 1) * 128 + c) * 2 + (k & 1);
        sW2f[base + 0] = v.x;
        sW2f[base + 2] = v.y;
        sW2f[base + 4] = v.z;
        sW2f[base + 6] = v.w;
    }

    // load X tile (64 rows x 128) with optional relu(x+b) op
    const float4* S4 = sel ? (const float4*)g_a : (const float4*)X;
    const float4* B4 = (const float4*)bias;
#pragma unroll
    for (int i = 0; i < 8; i++) {
        int idx = tid + 256 * i;          // float4 index within [64][32]
        int r = idx >> 5, c4 = idx & 31;
        int grow = row0 + r;
        float4 v = make_float4(0.f, 0.f, 0.f, 0.f);
        if (grow < NN) {
            v = S4[grow * 32 + c4];
            if (sel) {
                float4 b = B4[c4];
                v.x = fmaxf(v.x + b.x, 0.f);
                v.y = fmaxf(v.y + b.y, 0.f);
                v.z = fmaxf(v.z + b.z, 0.f);
                v.w = fmaxf(v.w + b.w, 0.f);
            }
        }
        ((float4*)sX)[idx] = v;
    }
    __syncthreads();

    int tx = tid & 31, ty = tid >> 5;
    int rb = ty * 8;                      // 8 rows per thread
    // cols handled by this thread: tx, tx+32, tx+64, tx+96  (conflict-free b64 W loads)
    unsigned long long acc2[8][4];
#pragma unroll
    for (int r = 0; r < 8; r++)
#pragma unroll
        for (int c = 0; c < 4; c++) acc2[r][c] = 0ull;   // {0.f, 0.f}

#pragma unroll 4
    for (int kp = 0; kp < 64; kp++) {
        unsigned long long wv[4], xv[8];
#pragma unroll
        for (int c = 0; c < 4; c++) wv[c] = sW2[kp * 128 + tx + 32 * c];
#pragma unroll
        for (int r = 0; r < 8; r++)
            xv[r] = *(const unsigned long long*)&sX[(rb + r) * DIM + kp * 2];
#pragma unroll
        for (int r = 0; r < 8; r++)
#pragma unroll
            for (int c = 0; c < 4; c++)
                asm("fma.rn.f32x2 %0, %1, %2, %0;"
                    : "+l"(acc2[r][c]) : "l"(xv[r]), "l"(wv[c]));
    }

#pragma unroll
    for (int r = 0; r < 8; r++) {
        int grow = row0 + rb + r;
        if (grow < NN) {
#pragma unroll
            for (int c = 0; c < 4; c++) {
                unsigned int lo = (unsigned int)acc2[r][c];
                unsigned int hi = (unsigned int)(acc2[r][c] >> 32);
                g_h[grow * DIM + tx + 32 * c] =
                    __uint_as_float(lo) + __uint_as_float(hi);
            }
        }
    }
}

// ---------------------------------------------------------------- gather aggregation
// one warp per dst node: g_a[d] = g_h[d]*dis[d]^2 + sum_in h[src]*norm
__global__ void k_gather() {
    int w = (blockIdx.x * blockDim.x + threadIdx.x) >> 5;
    int lane = threadIdx.x & 31;
    if (w >= NN) return;
    int beg = g_rowptr[w], end = g_rowptr[w + 1];
    float ds = g_dis[w];
    float d2 = ds * ds;
    float4 acc = ((const float4*)g_h)[w * 32 + lane];
    acc.x *= d2; acc.y *= d2; acc.z *= d2; acc.w *= d2;

    for (int j0 = beg; j0 < end; j0 += 32) {
        int idx = j0 + lane;
        int s = 0; float nm = 0.f;
        if (idx < end) { s = g_csrc[idx]; nm = g_cnorm[idx]; }
        int cnt = min(32, end - j0);
        for (int j = 0; j < cnt; j++) {
            int   ss = __shfl_sync(0xffffffffu, s, j);
            float nn = __shfl_sync(0xffffffffu, nm, j);
            float4 v = ((const float4*)g_h)[ss * 32 + lane];
            acc.x = fmaf(v.x, nn, acc.x);
            acc.y = fmaf(v.y, nn, acc.y);
            acc.z = fmaf(v.z, nn, acc.z);
            acc.w = fmaf(v.w, nn, acc.w);
        }
    }
    ((float4*)g_a)[w * 32 + lane] = acc;
}

// ---------------------------------------------------------------- pooling
// g_pool[batch[i]] += relu(g_a[i] + b2); g_cnt[batch[i]] += 1
__global__ void k_pool(const int* __restrict__ batch,
                       const float* __restrict__ b2) {
    int i4 = blockIdx.x * blockDim.x + threadIdx.x;
    if (i4 >= NN * 32) return;
    int node = i4 >> 5, c4 = i4 & 31;
    float4 v = ((const float4*)g_a)[i4];
    float4 b = ((const float4*)b2)[c4];
    v.x = fmaxf(v.x + b.x, 0.f);
    v.y = fmaxf(v.y + b.y, 0.f);
    v.z = fmaxf(v.z + b.z, 0.f);
    v.w = fmaxf(v.w + b.w, 0.f);
    int g = batch[node];
    float* p = g_pool + g * DIM + c4 * 4;
    asm volatile("red.global.add.v4.f32 [%0], {%1,%2,%3,%4};"
                 :: "l"(p), "f"(v.x), "f"(v.y), "f"(v.z), "f"(v.w)
                 : "memory");
    if (c4 == 0) atomicAdd(&g_cnt[g], 1);
}

// ---------------------------------------------------------------- final FC
__global__ void k_fc(const float* __restrict__ Wfc, const float* __restrict__ bfc,
                     float* __restrict__ out) {
    int t = threadIdx.x;   // 1024 = 64 graphs x 16 outputs
    int g = t >> 4, o = t & 15;
    float inv = 1.f / fmaxf((float)g_cnt[g], 1.f);
    float acc = 0.f;
#pragma unroll
    for (int c = 0; c < DIM; c++)
        acc = fmaf(g_pool[g * DIM + c], Wfc[c * OD + o], acc);
    out[g * OD + o] = acc * inv + bfc[o];
}

// ----------------------------------------------------------------
extern "C" void kernel_launch(void* const* d_in, const int* in_sizes, int n_in,
                              void* d_out, int out_size) {
    const float* x        = (const float*)d_in[0];
    const int*   ei       = (const int*)d_in[1];   // [2, E] int32
    const int*   batch    = (const int*)d_in[2];
    const float* W1 = (const float*)d_in[3];
    const float* b1 = (const float*)d_in[4];
    const float* W2 = (const float*)d_in[5];
    const float* b2 = (const float*)d_in[6];
    const float* Wfc = (const float*)d_in[7];
    const float* bfc = (const float*)d_in[8];
    float* out = (float*)d_out;

    const int* src = ei;
    const int* dst = ei + NE;

    const int smem_gemm = 64 * 128 * 8 + 64 * DIM * 4;   // 64KB W-pairs + 32KB X = 96 KB
    cudaFuncSetAttribute(k_gemm, cudaFuncAttributeMaxDynamicSharedMemorySize, smem_gemm);

    const int T = 256;
    int gb_n    = (NN + T - 1) / T;
    int gb_e    = (NE + T - 1) / T;
    int gb_gemm = (NN + 63) / 64;
    int gb_nd4  = (NN * 32 + T - 1) / T;       // node x float4 grid
    int gb_gw   = (NN * 32 + T - 1) / T;       // warp-per-node grid

    // degree + CSR build (reused by both layers)
    k_zero<<<gb_n, T>>>();
    k_deg<<<gb_e, T>>>(dst);
    k_scan1<<<SCAN_NB, SCAN_CH>>>();
    k_scan2<<<1, 128>>>();
    k_scan3<<<SCAN_NB, SCAN_CH>>>();
    k_fill<<<gb_e, T>>>(src, dst);

    // layer 1
    k_gemm<<<gb_gemm, T, smem_gemm>>>(x, W1, nullptr, 0);
    k_gather<<<gb_gw, T>>>();

    // layer 2 (relu+b1 folded into GEMM input load)
    k_gemm<<<gb_gemm, T, smem_gemm>>>(x, W2, b1, 1);
    k_gather<<<gb_gw, T>>>();

    // pooling (relu+b2 folded into load) + FC
    k_pool<<<gb_nd4, T>>>(batch, b2);
    k_fc<<<1, 1024>>>(Wfc, bfc, out);
}

// round 12
// speedup vs baseline: 1.1246x; 1.1246x over previous
#include <cuda_runtime.h>

#define NN 50000
#define NE 800000
#define NG 64
#define DIM 128
#define OD 16
#define SCAN_CH 512
#define SCAN_NB ((NN + SCAN_CH - 1) / SCAN_CH)   // 98

// Scratch (device globals — no allocation allowed)
__device__ __align__(16) float g_h[NN * DIM];     // GEMM output / agg input
__device__ __align__(16) float g_a[NN * DIM];     // aggregation result
__device__ float g_dis[NN];                       // deg^-1/2
__device__ int   g_deg[NN];
__device__ int   g_rowptr[NN + 1];
__device__ int   g_cur[NN];
__device__ int   g_csrc[NE];                      // src per CSR slot (grouped by dst)
__device__ float g_cnorm[NE];                     // dis[s]*dis[d] per CSR slot
__device__ int   g_bsum[SCAN_NB];
__device__ int   g_boff[SCAN_NB];
__device__ __align__(16) float g_pool[NG * DIM];
__device__ int   g_cnt[NG];

// ---------------------------------------------------------------- zero scratch
__global__ void k_zero() {
    int i = blockIdx.x * blockDim.x + threadIdx.x;
    if (i < NN) g_deg[i] = 0;
    if (i < NG * DIM) g_pool[i] = 0.f;
    if (i < NG) g_cnt[i] = 0;
}

// ---------------------------------------------------------------- degree
__global__ void k_deg(const int* __restrict__ dst) {
    int e = blockIdx.x * blockDim.x + threadIdx.x;
    if (e < NE) atomicAdd(&g_deg[dst[e]], 1);
}

// ---------------------------------------------------------------- CSR build: scan
__global__ void k_scan1() {            // per-block sums of g_deg
    __shared__ int s[SCAN_CH];
    int b = blockIdx.x, t = threadIdx.x, i = b * SCAN_CH + t;
    s[t] = (i < NN) ? g_deg[i] : 0;
    __syncthreads();
#pragma unroll
    for (int off = SCAN_CH / 2; off > 0; off >>= 1) {
        if (t < off) s[t] += s[t + off];
        __syncthreads();
    }
    if (t == 0) g_bsum[b] = s[0];
}

__global__ void k_scan2() {            // exclusive scan of block sums (1 block)
    __shared__ int s[SCAN_NB];
    int t = threadIdx.x;
    if (t < SCAN_NB) s[t] = g_bsum[t];
    __syncthreads();
    if (t == 0) {
        int acc = 0;
        for (int i = 0; i < SCAN_NB; i++) { g_boff[i] = acc; acc += s[i]; }
    }
}

__global__ void k_scan3() {            // intra-block exclusive scan + offset (+dis)
    __shared__ int s[SCAN_CH];
    int b = blockIdx.x, t = threadIdx.x, i = b * SCAN_CH + t;
    int v = (i < NN) ? g_deg[i] : 0;
    s[t] = v;
    __syncthreads();
#pragma unroll
    for (int off = 1; off < SCAN_CH; off <<= 1) {
        int x = (t >= off) ? s[t - off] : 0;
        __syncthreads();
        s[t] += x;
        __syncthreads();
    }
    int excl = s[t] - v + g_boff[b];
    if (i < NN) {
        g_rowptr[i] = excl;
        g_cur[i] = excl;
        g_dis[i] = rsqrtf((float)(v + 1));   // +1 self loop, always > 0
    }
    if (i == NN - 1) g_rowptr[NN] = excl + v;
}

// ---------------------------------------------------------------- CSR fill
__global__ void k_fill(const int* __restrict__ src, const int* __restrict__ dst) {
    int e = blockIdx.x * blockDim.x + threadIdx.x;
    if (e >= NE) return;
    int s = src[e], d = dst[e];
    int p = atomicAdd(&g_cur[d], 1);
    g_csrc[p] = s;
    g_cnorm[p] = g_dis[s] * g_dis[d];
}

// ---------------------------------------------------------------- GEMM
// g_h[M,128] = op(src)[M,128] @ W[128,128]
// sel==0: src = X (raw).  sel==1: src = relu(g_a + bias)
__global__ void k_gemm(const float* __restrict__ X, const float* __restrict__ W,
                       const float* __restrict__ bias, int sel) {
    extern __shared__ float smem[];
    float* sW = smem;                 // [128][128]
    float* sX = smem + DIM * DIM;     // [64][128]
    int tid = threadIdx.x;            // 256 threads
    int row0 = blockIdx.x * 64;

    const float4* W4 = (const float4*)W;
    float4* sW4 = (float4*)sW;
#pragma unroll
    for (int i = 0; i < 16; i++) sW4[tid + 256 * i] = W4[tid + 256 * i];

    const float4* S4 = sel ? (const float4*)g_a : (const float4*)X;
    const float4* B4 = (const float4*)bias;
#pragma unroll
    for (int i = 0; i < 8; i++) {
        int idx = tid + 256 * i;          // float4 index within [64][32]
        int r = idx >> 5, c4 = idx & 31;
        int grow = row0 + r;
        float4 v = make_float4(0.f, 0.f, 0.f, 0.f);
        if (grow < NN) {
            v = S4[grow * 32 + c4];
            if (sel) {
                float4 b = B4[c4];
                v.x = fmaxf(v.x + b.x, 0.f);
                v.y = fmaxf(v.y + b.y, 0.f);
                v.z = fmaxf(v.z + b.z, 0.f);
                v.w = fmaxf(v.w + b.w, 0.f);
            }
        }
        ((float4*)sX)[idx] = v;
    }
    __syncthreads();

    int tx = tid & 31, ty = tid >> 5;
    int col = tx * 4;      // 4 cols
    int rb = ty * 8;       // 8 rows
    float acc[8][4];
#pragma unroll
    for (int r = 0; r < 8; r++)
#pragma unroll
        for (int c = 0; c < 4; c++) acc[r][c] = 0.f;

#pragma unroll 8
    for (int k = 0; k < DIM; k++) {
        float4 w = *(const float4*)&sW[k * DIM + col];
#pragma unroll
        for (int r = 0; r < 8; r++) {
            float xv = sX[(rb + r) * DIM + k];
            acc[r][0] = fmaf(xv, w.x, acc[r][0]);
            acc[r][1] = fmaf(xv, w.y, acc[r][1]);
            acc[r][2] = fmaf(xv, w.z, acc[r][2]);
            acc[r][3] = fmaf(xv, w.w, acc[r][3]);
        }
    }

#pragma unroll
    for (int r = 0; r < 8; r++) {
        int grow = row0 + rb + r;
        if (grow < NN)
            *(float4*)&g_h[grow * DIM + col] =
                make_float4(acc[r][0], acc[r][1], acc[r][2], acc[r][3]);
    }
}

// ---------------------------------------------------------------- gather aggregation
// one warp per dst node: g_a[d] = g_h[d]*dis[d]^2 + sum_in h[src]*norm
__global__ void k_gather() {
    int w = (blockIdx.x * blockDim.x + threadIdx.x) >> 5;
    int lane = threadIdx.x & 31;
    if (w >= NN) return;
    int beg = g_rowptr[w], end = g_rowptr[w + 1];
    float ds = g_dis[w];
    float d2 = ds * ds;
    float4 acc = ((const float4*)g_h)[w * 32 + lane];
    acc.x *= d2; acc.y *= d2; acc.z *= d2; acc.w *= d2;

    for (int j0 = beg; j0 < end; j0 += 32) {
        int idx = j0 + lane;
        int s = 0; float nm = 0.f;
        if (idx < end) { s = g_csrc[idx]; nm = g_cnorm[idx]; }
        int cnt = min(32, end - j0);
        for (int j = 0; j < cnt; j++) {
            int   ss = __shfl_sync(0xffffffffu, s, j);
            float nn = __shfl_sync(0xffffffffu, nm, j);
            float4 v = ((const float4*)g_h)[ss * 32 + lane];
            acc.x = fmaf(v.x, nn, acc.x);
            acc.y = fmaf(v.y, nn, acc.y);
            acc.z = fmaf(v.z, nn, acc.z);
            acc.w = fmaf(v.w, nn, acc.w);
        }
    }
    ((float4*)g_a)[w * 32 + lane] = acc;
}

// ---------------------------------------------------------------- pooling
// g_pool[batch[i]] += relu(g_a[i] + b2); g_cnt[batch[i]] += 1
__global__ void k_pool(const int* __restrict__ batch,
                       const float* __restrict__ b2) {
    int i4 = blockIdx.x * blockDim.x + threadIdx.x;
    if (i4 >= NN * 32) return;
    int node = i4 >> 5, c4 = i4 & 31;
    float4 v = ((const float4*)g_a)[i4];
    float4 b = ((const float4*)b2)[c4];
    v.x = fmaxf(v.x + b.x, 0.f);
    v.y = fmaxf(v.y + b.y, 0.f);
    v.z = fmaxf(v.z + b.z, 0.f);
    v.w = fmaxf(v.w + b.w, 0.f);
    int g = batch[node];
    float* p = g_pool + g * DIM + c4 * 4;
    asm volatile("red.global.add.v4.f32 [%0], {%1,%2,%3,%4};"
                 :: "l"(p), "f"(v.x), "f"(v.y), "f"(v.z), "f"(v.w)
                 : "memory");
    if (c4 == 0) atomicAdd(&g_cnt[g], 1);
}

// ---------------------------------------------------------------- final FC
__global__ void k_fc(const float* __restrict__ Wfc, const float* __restrict__ bfc,
                     float* __restrict__ out) {
    int t = threadIdx.x;   // 1024 = 64 graphs x 16 outputs
    int g = t >> 4, o = t & 15;
    float inv = 1.f / fmaxf((float)g_cnt[g], 1.f);
    float acc = 0.f;
#pragma unroll
    for (int c = 0; c < DIM; c++)
        acc = fmaf(g_pool[g * DIM + c], Wfc[c * OD + o], acc);
    out[g * OD + o] = acc * inv + bfc[o];
}

// ----------------------------------------------------------------
extern "C" void kernel_launch(void* const* d_in, const int* in_sizes, int n_in,
                              void* d_out, int out_size) {
    const float* x        = (const float*)d_in[0];
    const int*   ei       = (const int*)d_in[1];   // [2, E] int32
    const int*   batch    = (const int*)d_in[2];
    const float* W1 = (const float*)d_in[3];
    const float* b1 = (const float*)d_in[4];
    const float* W2 = (const float*)d_in[5];
    const float* b2 = (const float*)d_in[6];
    const float* Wfc = (const float*)d_in[7];
    const float* bfc = (const float*)d_in[8];
    float* out = (float*)d_out;

    const int* src = ei;
    const int* dst = ei + NE;

    // One-time host-side resources (streams/events are not device memory;
    // identical launch pattern every call).
    static cudaStream_t s_build = nullptr;
    static cudaEvent_t  ev_fork = nullptr, ev_join = nullptr;
    if (!s_build) {
        cudaStreamCreateWithFlags(&s_build, cudaStreamNonBlocking);
        cudaEventCreateWithFlags(&ev_fork, cudaEventDisableTiming);
        cudaEventCreateWithFlags(&ev_join, cudaEventDisableTiming);
    }

    const int smem_gemm = (DIM * DIM + 64 * DIM) * (int)sizeof(float);  // 96 KB
    cudaFuncSetAttribute(k_gemm, cudaFuncAttributeMaxDynamicSharedMemorySize, smem_gemm);

    const int T = 256;
    int gb_n    = (NN + T - 1) / T;
    int gb_e    = (NE + T - 1) / T;
    int gb_gemm = (NN + 63) / 64;
    int gb_nd4  = (NN * 32 + T - 1) / T;       // node x float4 grid
    int gb_gw   = (NN * 32 + T - 1) / T;       // warp-per-node grid

    // Fork: CSR build chain runs on s_build, overlapped with gemm layer 1.
    cudaEventRecord(ev_fork, 0);
    cudaStreamWaitEvent(s_build, ev_fork, 0);

    // build branch (independent of gemm1)
    k_zero <<<gb_n, T, 0, s_build>>>();
    k_deg  <<<gb_e, T, 0, s_build>>>(dst);
    k_scan1<<<SCAN_NB, SCAN_CH, 0, s_build>>>();
    k_scan2<<<1, 128, 0, s_build>>>();
    k_scan3<<<SCAN_NB, SCAN_CH, 0, s_build>>>();
    k_fill <<<gb_e, T, 0, s_build>>>(src, dst);
    cudaEventRecord(ev_join, s_build);

    // main branch: gemm layer 1 (depends only on x, W1)
    k_gemm<<<gb_gemm, T, smem_gemm>>>(x, W1, nullptr, 0);

    // join: gather needs both gemm1 output and the CSR
    cudaStreamWaitEvent(0, ev_join, 0);
    k_gather<<<gb_gw, T>>>();

    // layer 2 (relu+b1 folded into GEMM input load)
    k_gemm<<<gb_gemm, T, smem_gemm>>>(x, W2, b1, 1);
    k_gather<<<gb_gw, T>>>();

    // pooling (relu+b2 folded into load) + FC
    k_pool<<<gb_nd4, T>>>(batch, b2);
    k_fc<<<1, 1024>>>(Wfc, bfc, out);
}

// round 13
// speedup vs baseline: 1.1888x; 1.0571x over previous
#include <cuda_runtime.h>

#define NN 50000
#define NE 800000
#define NG 64
#define DIM 128
#define OD 16
#define SCAN_CH 512
#define SCAN_NB ((NN + SCAN_CH - 1) / SCAN_CH)   // 98

// Scratch (device globals — no allocation allowed)
__device__ __align__(16) float g_h[NN * DIM];     // GEMM output / agg input
__device__ __align__(16) float g_a[NN * DIM];     // aggregation result
__device__ float g_dis[NN];                       // deg^-1/2
__device__ int   g_deg[NN];
__device__ int   g_rowptr[NN + 1];
__device__ int   g_cur[NN];
__device__ int   g_csrc[NE];                      // src per CSR slot (grouped by dst)
__device__ float g_cnorm[NE];                     // dis[s]*dis[d] per CSR slot
__device__ int   g_bsum[SCAN_NB];
__device__ int   g_boff[SCAN_NB];
__device__ __align__(16) float g_pool[NG * DIM];
__device__ int   g_cnt[NG];

// ---------------------------------------------------------------- zero scratch
__global__ void k_zero() {
    int i = blockIdx.x * blockDim.x + threadIdx.x;
    if (i < NN) g_deg[i] = 0;
    if (i < NG * DIM) g_pool[i] = 0.f;
    if (i < NG) g_cnt[i] = 0;
}

// ---------------------------------------------------------------- degree
__global__ void k_deg(const int* __restrict__ dst) {
    int e = blockIdx.x * blockDim.x + threadIdx.x;
    if (e < NE) atomicAdd(&g_deg[dst[e]], 1);
}

// ---------------------------------------------------------------- CSR build: scan
__global__ void k_scan1() {            // per-block sums of g_deg
    __shared__ int s[SCAN_CH];
    int b = blockIdx.x, t = threadIdx.x, i = b * SCAN_CH + t;
    s[t] = (i < NN) ? g_deg[i] : 0;
    __syncthreads();
#pragma unroll
    for (int off = SCAN_CH / 2; off > 0; off >>= 1) {
        if (t < off) s[t] += s[t + off];
        __syncthreads();
    }
    if (t == 0) g_bsum[b] = s[0];
}

__global__ void k_scan2() {            // exclusive scan of block sums (1 block)
    __shared__ int s[SCAN_NB];
    int t = threadIdx.x;
    if (t < SCAN_NB) s[t] = g_bsum[t];
    __syncthreads();
    if (t == 0) {
        int acc = 0;
        for (int i = 0; i < SCAN_NB; i++) { g_boff[i] = acc; acc += s[i]; }
    }
}

__global__ void k_scan3() {            // intra-block exclusive scan + offset (+dis)
    __shared__ int s[SCAN_CH];
    int b = blockIdx.x, t = threadIdx.x, i = b * SCAN_CH + t;
    int v = (i < NN) ? g_deg[i] : 0;
    s[t] = v;
    __syncthreads();
#pragma unroll
    for (int off = 1; off < SCAN_CH; off <<= 1) {
        int x = (t >= off) ? s[t - off] : 0;
        __syncthreads();
        s[t] += x;
        __syncthreads();
    }
    int excl = s[t] - v + g_boff[b];
    if (i < NN) {
        g_rowptr[i] = excl;
        g_cur[i] = excl;
        g_dis[i] = rsqrtf((float)(v + 1));   // +1 self loop, always > 0
    }
    if (i == NN - 1) g_rowptr[NN] = excl + v;
}

// ---------------------------------------------------------------- CSR fill
__global__ void k_fill(const int* __restrict__ src, const int* __restrict__ dst) {
    int e = blockIdx.x * blockDim.x + threadIdx.x;
    if (e >= NE) return;
    int s = src[e], d = dst[e];
    int p = atomicAdd(&g_cur[d], 1);
    g_csrc[p] = s;
    g_cnorm[p] = g_dis[s] * g_dis[d];
}

// ---------------------------------------------------------------- GEMM
// g_h[M,128] = op(src)[M,128] @ W[128,128]
// sel==0: src = X (raw).  sel==1: src = relu(g_a + bias)
__global__ void k_gemm(const float* __restrict__ X, const float* __restrict__ W,
                       const float* __restrict__ bias, int sel) {
    extern __shared__ float smem[];
    float* sW = smem;                 // [128][128]
    float* sX = smem + DIM * DIM;     // [64][128]
    int tid = threadIdx.x;            // 256 threads
    int row0 = blockIdx.x * 64;

    const float4* W4 = (const float4*)W;
    float4* sW4 = (float4*)sW;
#pragma unroll
    for (int i = 0; i < 16; i++) sW4[tid + 256 * i] = W4[tid + 256 * i];

    const float4* S4 = sel ? (const float4*)g_a : (const float4*)X;
    const float4* B4 = (const float4*)bias;
#pragma unroll
    for (int i = 0; i < 8; i++) {
        int idx = tid + 256 * i;          // float4 index within [64][32]
        int r = idx >> 5, c4 = idx & 31;
        int grow = row0 + r;
        float4 v = make_float4(0.f, 0.f, 0.f, 0.f);
        if (grow < NN) {
            v = S4[grow * 32 + c4];
            if (sel) {
                float4 b = B4[c4];
                v.x = fmaxf(v.x + b.x, 0.f);
                v.y = fmaxf(v.y + b.y, 0.f);
                v.z = fmaxf(v.z + b.z, 0.f);
                v.w = fmaxf(v.w + b.w, 0.f);
            }
        }
        ((float4*)sX)[idx] = v;
    }
    __syncthreads();

    int tx = tid & 31, ty = tid >> 5;
    int col = tx * 4;      // 4 cols
    int rb = ty * 8;       // 8 rows
    float acc[8][4];
#pragma unroll
    for (int r = 0; r < 8; r++)
#pragma unroll
        for (int c = 0; c < 4; c++) acc[r][c] = 0.f;

#pragma unroll 8
    for (int k = 0; k < DIM; k++) {
        float4 w = *(const float4*)&sW[k * DIM + col];
#pragma unroll
        for (int r = 0; r < 8; r++) {
            float xv = sX[(rb + r) * DIM + k];
            acc[r][0] = fmaf(xv, w.x, acc[r][0]);
            acc[r][1] = fmaf(xv, w.y, acc[r][1]);
            acc[r][2] = fmaf(xv, w.z, acc[r][2]);
            acc[r][3] = fmaf(xv, w.w, acc[r][3]);
        }
    }

#pragma unroll
    for (int r = 0; r < 8; r++) {
        int grow = row0 + rb + r;
        if (grow < NN)
            *(float4*)&g_h[grow * DIM + col] =
                make_float4(acc[r][0], acc[r][1], acc[r][2], acc[r][3]);
    }
}

// ---------------------------------------------------------------- gather core
// one warp per dst node: acc = g_h[d]*dis[d]^2 + sum_in h[src]*norm
// inner loop unrolled x4 for MLP (4 independent LDG.128 in flight).
__device__ __forceinline__ float4 gather_row(int w, int lane) {
    int beg = g_rowptr[w], end = g_rowptr[w + 1];
    float ds = g_dis[w];
    float d2 = ds * ds;
    float4 acc = ((const float4*)g_h)[w * 32 + lane];
    acc.x *= d2; acc.y *= d2; acc.z *= d2; acc.w *= d2;

    for (int j0 = beg; j0 < end; j0 += 32) {
        int idx = j0 + lane;
        int s = 0; float nm = 0.f;
        if (idx < end) { s = g_csrc[idx]; nm = g_cnorm[idx]; }
        int cnt = min(32, end - j0);
        int j = 0;
        for (; j + 4 <= cnt; j += 4) {
            int   s0 = __shfl_sync(0xffffffffu, s, j);
            int   s1 = __shfl_sync(0xffffffffu, s, j + 1);
            int   s2 = __shfl_sync(0xffffffffu, s, j + 2);
            int   s3 = __shfl_sync(0xffffffffu, s, j + 3);
            float n0 = __shfl_sync(0xffffffffu, nm, j);
            float n1 = __shfl_sync(0xffffffffu, nm, j + 1);
            float n2 = __shfl_sync(0xffffffffu, nm, j + 2);
            float n3 = __shfl_sync(0xffffffffu, nm, j + 3);
            float4 v0 = ((const float4*)g_h)[s0 * 32 + lane];
            float4 v1 = ((const float4*)g_h)[s1 * 32 + lane];
            float4 v2 = ((const float4*)g_h)[s2 * 32 + lane];
            float4 v3 = ((const float4*)g_h)[s3 * 32 + lane];
            acc.x = fmaf(v0.x, n0, acc.x); acc.y = fmaf(v0.y, n0, acc.y);
            acc.z = fmaf(v0.z, n0, acc.z); acc.w = fmaf(v0.w, n0, acc.w);
            acc.x = fmaf(v1.x, n1, acc.x); acc.y = fmaf(v1.y, n1, acc.y);
            acc.z = fmaf(v1.z, n1, acc.z); acc.w = fmaf(v1.w, n1, acc.w);
            acc.x = fmaf(v2.x, n2, acc.x); acc.y = fmaf(v2.y, n2, acc.y);
            acc.z = fmaf(v2.z, n2, acc.z); acc.w = fmaf(v2.w, n2, acc.w);
            acc.x = fmaf(v3.x, n3, acc.x); acc.y = fmaf(v3.y, n3, acc.y);
            acc.z = fmaf(v3.z, n3, acc.z); acc.w = fmaf(v3.w, n3, acc.w);
        }
        for (; j < cnt; j++) {
            int   ss = __shfl_sync(0xffffffffu, s, j);
            float nn = __shfl_sync(0xffffffffu, nm, j);
            float4 v = ((const float4*)g_h)[ss * 32 + lane];
            acc.x = fmaf(v.x, nn, acc.x);
            acc.y = fmaf(v.y, nn, acc.y);
            acc.z = fmaf(v.z, nn, acc.z);
            acc.w = fmaf(v.w, nn, acc.w);
        }
    }
    return acc;
}

// layer 1: write aggregation to g_a
__global__ void k_gather() {
    int w = (blockIdx.x * blockDim.x + threadIdx.x) >> 5;
    int lane = threadIdx.x & 31;
    if (w >= NN) return;
    ((float4*)g_a)[w * 32 + lane] = gather_row(w, lane);
}

// layer 2 fused with pooling: relu(acc + b2) accumulated straight into g_pool
__global__ void k_gather_pool(const int* __restrict__ batch,
                              const float* __restrict__ b2) {
    int w = (blockIdx.x * blockDim.x + threadIdx.x) >> 5;
    int lane = threadIdx.x & 31;
    if (w >= NN) return;
    float4 acc = gather_row(w, lane);
    float4 b = ((const float4*)b2)[lane];
    acc.x = fmaxf(acc.x + b.x, 0.f);
    acc.y = fmaxf(acc.y + b.y, 0.f);
    acc.z = fmaxf(acc.z + b.z, 0.f);
    acc.w = fmaxf(acc.w + b.w, 0.f);
    int g = batch[w];
    float* p = g_pool + g * DIM + lane * 4;
    asm volatile("red.global.add.v4.f32 [%0], {%1,%2,%3,%4};"
                 :: "l"(p), "f"(acc.x), "f"(acc.y), "f"(acc.z), "f"(acc.w)
                 : "memory");
    if (lane == 0) atomicAdd(&g_cnt[g], 1);
}

// ---------------------------------------------------------------- final FC
__global__ void k_fc(const float* __restrict__ Wfc, const float* __restrict__ bfc,
                     float* __restrict__ out) {
    int t = threadIdx.x;   // 1024 = 64 graphs x 16 outputs
    int g = t >> 4, o = t & 15;
    float inv = 1.f / fmaxf((float)g_cnt[g], 1.f);
    float acc = 0.f;
#pragma unroll
    for (int c = 0; c < DIM; c++)
        acc = fmaf(g_pool[g * DIM + c], Wfc[c * OD + o], acc);
    out[g * OD + o] = acc * inv + bfc[o];
}

// ----------------------------------------------------------------
extern "C" void kernel_launch(void* const* d_in, const int* in_sizes, int n_in,
                              void* d_out, int out_size) {
    const float* x        = (const float*)d_in[0];
    const int*   ei       = (const int*)d_in[1];   // [2, E] int32
    const int*   batch    = (const int*)d_in[2];
    const float* W1 = (const float*)d_in[3];
    const float* b1 = (const float*)d_in[4];
    const float* W2 = (const float*)d_in[5];
    const float* b2 = (const float*)d_in[6];
    const float* Wfc = (const float*)d_in[7];
    const float* bfc = (const float*)d_in[8];
    float* out = (float*)d_out;

    const int* src = ei;
    const int* dst = ei + NE;

    // One-time host-side resources (streams/events are not device memory;
    // identical launch pattern every call).
    static cudaStream_t s_build = nullptr;
    static cudaEvent_t  ev_fork = nullptr, ev_join = nullptr;
    if (!s_build) {
        cudaStreamCreateWithFlags(&s_build, cudaStreamNonBlocking);
        cudaEventCreateWithFlags(&ev_fork, cudaEventDisableTiming);
        cudaEventCreateWithFlags(&ev_join, cudaEventDisableTiming);
    }

    const int smem_gemm = (DIM * DIM + 64 * DIM) * (int)sizeof(float);  // 96 KB
    cudaFuncSetAttribute(k_gemm, cudaFuncAttributeMaxDynamicSharedMemorySize, smem_gemm);

    const int T = 256;
    int gb_n    = (NN + T - 1) / T;
    int gb_e    = (NE + T - 1) / T;
    int gb_gemm = (NN + 63) / 64;
    int gb_gw   = (NN * 32 + T - 1) / T;       // warp-per-node grid

    // Fork: CSR build chain runs on s_build, overlapped with gemm layer 1.
    cudaEventRecord(ev_fork, 0);
    cudaStreamWaitEvent(s_build, ev_fork, 0);

    // build branch (independent of gemm1)
    k_zero <<<gb_n, T, 0, s_build>>>();
    k_deg  <<<gb_e, T, 0, s_build>>>(dst);
    k_scan1<<<SCAN_NB, SCAN_CH, 0, s_build>>>();
    k_scan2<<<1, 128, 0, s_build>>>();
    k_scan3<<<SCAN_NB, SCAN_CH, 0, s_build>>>();
    k_fill <<<gb_e, T, 0, s_build>>>(src, dst);
    cudaEventRecord(ev_join, s_build);

    // main branch: gemm layer 1 (depends only on x, W1)
    k_gemm<<<gb_gemm, T, smem_gemm>>>(x, W1, nullptr, 0);

    // join: gather needs both gemm1 output and the CSR
    cudaStreamWaitEvent(0, ev_join, 0);
    k_gather<<<gb_gw, T>>>();

    // layer 2 (relu+b1 folded into GEMM input load), gather fused with pooling
    k_gemm<<<gb_gemm, T, smem_gemm>>>(x, W2, b1, 1);
    k_gather_pool<<<gb_gw, T>>>(batch, b2);

    // final FC
    k_fc<<<1, 1024>>>(Wfc, bfc, out);
}